// round 1
// baseline (speedup 1.0000x reference)
#include <cuda_runtime.h>
#include <math.h>

// Problem constants
#define BB 4
#define TT 1024
#define MM 512
#define HH 8
#define DK 64
#define DV 64
#define NTOK (BB*TT)          // 4096
#define PROJ (HH*DK)          // 512

// Scratch (no cudaMalloc allowed)
__device__ float g_qf[NTOK*PROJ];
__device__ float g_kf[NTOK*PROJ];
__device__ float g_v [NTOK*PROJ];
__device__ float g_o [NTOK*PROJ];

enum { MODE_PHI = 0, MODE_RAW = 1, MODE_GATE = 2 };

// ---------------------------------------------------------------------------
// C[Mrows,N] = A[Mrows,Kd] @ Bw[Kd,N] with fused epilogue.
// BM=BN=128, BK=8, 256 threads, 8x8 microtile.
// ---------------------------------------------------------------------------
__global__ __launch_bounds__(256) void sgemm_ep(
    const float* __restrict__ A, const float* __restrict__ Bw,
    float* __restrict__ C, const float* __restrict__ bias,
    int mode, int N, int Kd)
{
    __shared__ float As[8][128];
    __shared__ float Bs[8][128];

    const int tid  = threadIdx.x;
    const int bRow = blockIdx.y, bCol = blockIdx.x;
    const int rowBase = (tid / 16) * 8;
    const int colBase = (tid % 16) * 8;

    float acc[8][8] = {};

    const int aRow  = tid / 2,  aCol  = (tid % 2) * 4;
    const int bRowL = tid / 32, bColL = (tid % 32) * 4;
    const float* Ap = A  + (size_t)(bRow * 128 + aRow) * Kd + aCol;
    const float* Bp = Bw + (size_t)bRowL * N + bCol * 128 + bColL;

    for (int k0 = 0; k0 < Kd; k0 += 8) {
        float4 av = *(const float4*)(Ap + k0);
        As[aCol + 0][aRow] = av.x;
        As[aCol + 1][aRow] = av.y;
        As[aCol + 2][aRow] = av.z;
        As[aCol + 3][aRow] = av.w;
        float4 bv = *(const float4*)(Bp + (size_t)k0 * N);
        *(float4*)&Bs[bRowL][bColL] = bv;
        __syncthreads();

        #pragma unroll
        for (int k = 0; k < 8; k++) {
            float ar[8], br[8];
            #pragma unroll
            for (int i = 0; i < 8; i++) ar[i] = As[k][rowBase + i];
            #pragma unroll
            for (int j = 0; j < 8; j++) br[j] = Bs[k][colBase + j];
            #pragma unroll
            for (int i = 0; i < 8; i++)
                #pragma unroll
                for (int j = 0; j < 8; j++)
                    acc[i][j] += ar[i] * br[j];
        }
        __syncthreads();
    }

    const int row0 = bRow * 128 + rowBase;
    const int col0 = bCol * 128 + colBase;
    #pragma unroll
    for (int i = 0; i < 8; i++) {
        #pragma unroll
        for (int j = 0; j < 8; j++) {
            size_t idx = (size_t)(row0 + i) * N + (col0 + j);
            float v = acc[i][j];
            if (mode == MODE_PHI) {
                // phi(x) = elu(x)+1 = x>0 ? x+1 : exp(x)
                C[idx] = (v > 0.f) ? (v + 1.f) : expf(v);
            } else if (mode == MODE_RAW) {
                C[idx] = v;
            } else { // MODE_GATE: C holds raw v-projection; multiply by 2*sigmoid(g)
                float g = v + bias[col0 + j];
                C[idx] = C[idx] * (2.f / (1.f + expf(-g)));
            }
        }
    }
}

// ---------------------------------------------------------------------------
// Causal phi-kernel attention per (b,h, 64-row tile).
// Phase 1: numer += S_causal @ Vg, rowsum += rowsum(S_causal).
// Phase 2: recompute S tiles, write att_map = S/(rowsum+eps); zero upper tri.
// Dynamic smem: 4 x [64][65] tiles + rowsum[64].
// ---------------------------------------------------------------------------
__global__ __launch_bounds__(256) void attn_kernel(
    const float* __restrict__ qf, const float* __restrict__ kf,
    const float* __restrict__ vg, float* __restrict__ o,
    float* __restrict__ att)
{
    extern __shared__ float sm[];
    float (*Qs)[65] = (float(*)[65])(sm);
    float (*Ks)[65] = (float(*)[65])(sm + 64 * 65);
    float (*Vs)[65] = (float(*)[65])(sm + 2 * 64 * 65);
    float (*Ss)[65] = (float(*)[65])(sm + 3 * 64 * 65);
    float* rowsum   = sm + 4 * 64 * 65;

    const int tid = threadIdx.x;
    const int tileT = blockIdx.x;   // 0..15
    const int h = blockIdx.y;       // 0..7
    const int b = blockIdx.z;       // 0..3
    const int t0 = tileT * 64;

    const int tx = tid % 16, ty = tid / 16;
    const int r0 = ty * 4, c0 = tx * 4;

    // Load Q tile (coalesced)
    for (int e = tid; e < 64 * 64; e += 256) {
        int r = e >> 6, c = e & 63;
        Qs[r][c] = qf[((size_t)(b * TT + t0 + r)) * PROJ + h * DK + c];
    }
    if (tid < 64) rowsum[tid] = 0.f;

    float acc[4][4] = {};

    // ---- Phase 1: causal column tiles ----
    for (int jt = 0; jt <= tileT; jt++) {
        __syncthreads();   // prior-iter smem reads complete
        const int s0 = jt * 64;
        for (int e = tid; e < 64 * 64; e += 256) {
            int r = e >> 6, c = e & 63;
            size_t gi = ((size_t)(b * TT + s0 + r)) * PROJ + h * DK + c;
            Ks[r][c] = kf[gi];
            Vs[r][c] = vg[gi];
        }
        __syncthreads();

        float s[4][4] = {};
        #pragma unroll 8
        for (int kk = 0; kk < 64; kk++) {
            float qv[4], kv[4];
            #pragma unroll
            for (int i = 0; i < 4; i++) qv[i] = Qs[r0 + i][kk];
            #pragma unroll
            for (int j = 0; j < 4; j++) kv[j] = Ks[c0 + j][kk];
            #pragma unroll
            for (int i = 0; i < 4; i++)
                #pragma unroll
                for (int j = 0; j < 4; j++)
                    s[i][j] += qv[i] * kv[j];
        }
        if (jt == tileT) {
            #pragma unroll
            for (int i = 0; i < 4; i++)
                #pragma unroll
                for (int j = 0; j < 4; j++)
                    if (c0 + j > r0 + i) s[i][j] = 0.f;
        }
        #pragma unroll
        for (int i = 0; i < 4; i++)
            #pragma unroll
            for (int j = 0; j < 4; j++)
                Ss[r0 + i][c0 + j] = s[i][j];
        __syncthreads();

        if (tid < 64) {
            float rs = 0.f;
            #pragma unroll 8
            for (int c = 0; c < 64; c++) rs += Ss[tid][c];
            rowsum[tid] += rs;
        }
        #pragma unroll 8
        for (int cc = 0; cc < 64; cc++) {
            float sv[4], vv[4];
            #pragma unroll
            for (int i = 0; i < 4; i++) sv[i] = Ss[r0 + i][cc];
            #pragma unroll
            for (int j = 0; j < 4; j++) vv[j] = Vs[cc][c0 + j];
            #pragma unroll
            for (int i = 0; i < 4; i++)
                #pragma unroll
                for (int j = 0; j < 4; j++)
                    acc[i][j] += sv[i] * vv[j];
        }
    }
    __syncthreads();

    float denom[4];
    #pragma unroll
    for (int i = 0; i < 4; i++) denom[i] = rowsum[r0 + i] + 1e-6f;

    // Write numer/denom -> g_o [B,T,H*V]
    #pragma unroll
    for (int i = 0; i < 4; i++)
        #pragma unroll
        for (int j = 0; j < 4; j++)
            o[((size_t)(b * TT + t0 + r0 + i)) * PROJ + h * DV + c0 + j] =
                acc[i][j] / denom[i];

    // ---- Phase 2: write att_map ----
    const size_t attBase = ((size_t)(b * HH + h)) * TT * TT;
    for (int jt = 0; jt < TT / 64; jt++) {
        const int s0 = jt * 64;
        if (jt <= tileT) {
            __syncthreads();
            for (int e = tid; e < 64 * 64; e += 256) {
                int r = e >> 6, c = e & 63;
                Ks[r][c] = kf[((size_t)(b * TT + s0 + r)) * PROJ + h * DK + c];
            }
            __syncthreads();
            float s[4][4] = {};
            #pragma unroll 8
            for (int kk = 0; kk < 64; kk++) {
                float qv[4], kv[4];
                #pragma unroll
                for (int i = 0; i < 4; i++) qv[i] = Qs[r0 + i][kk];
                #pragma unroll
                for (int j = 0; j < 4; j++) kv[j] = Ks[c0 + j][kk];
                #pragma unroll
                for (int i = 0; i < 4; i++)
                    #pragma unroll
                    for (int j = 0; j < 4; j++)
                        s[i][j] += qv[i] * kv[j];
            }
            #pragma unroll
            for (int i = 0; i < 4; i++)
                #pragma unroll
                for (int j = 0; j < 4; j++) {
                    float v = ((jt == tileT) && (c0 + j > r0 + i)) ? 0.f
                              : s[i][j] / denom[i];
                    Ss[r0 + i][c0 + j] = v;
                }
            __syncthreads();
            for (int e = tid; e < 64 * 64; e += 256) {
                int r = e >> 6, c = e & 63;
                att[attBase + (size_t)(t0 + r) * TT + s0 + c] = Ss[r][c];
            }
        } else {
            // strictly above the diagonal: zeros (d_out is poisoned)
            for (int e = tid; e < 64 * 64; e += 256) {
                int r = e >> 6, c = e & 63;
                att[attBase + (size_t)(t0 + r) * TT + s0 + c] = 0.f;
            }
        }
    }
}

// ---------------------------------------------------------------------------
extern "C" void kernel_launch(void* const* d_in, const int* in_sizes, int n_in,
                              void* d_out, int out_size)
{
    const float* query = (const float*)d_in[0];
    const float* key   = (const float*)d_in[1];
    const float* value = (const float*)d_in[2];
    const float* Wq    = (const float*)d_in[3];
    const float* Wk    = (const float*)d_in[4];
    const float* Wv    = (const float*)d_in[5];
    const float* Wg    = (const float*)d_in[6];
    const float* bg    = (const float*)d_in[7];
    const float* Wo    = (const float*)d_in[8];

    float* out = (float*)d_out;                       // [B,T,M]
    float* att = out + (size_t)NTOK * MM;             // [B,H,T,T]

    float *qf, *kf, *vg, *ov;
    cudaGetSymbolAddress((void**)&qf, g_qf);
    cudaGetSymbolAddress((void**)&kf, g_kf);
    cudaGetSymbolAddress((void**)&vg, g_v);
    cudaGetSymbolAddress((void**)&ov, g_o);

    const int ATTN_SMEM = (4 * 64 * 65 + 64) * (int)sizeof(float); // 66816 B
    cudaFuncSetAttribute(attn_kernel,
                         cudaFuncAttributeMaxDynamicSharedMemorySize, ATTN_SMEM);

    dim3 gg(PROJ / 128, NTOK / 128);   // (4, 32)
    dim3 bb(256);

    // Projections
    sgemm_ep<<<gg, bb>>>(query, Wq, qf, nullptr, MODE_PHI,  PROJ, MM);
    sgemm_ep<<<gg, bb>>>(key,   Wk, kf, nullptr, MODE_PHI,  PROJ, MM);
    sgemm_ep<<<gg, bb>>>(value, Wv, vg, nullptr, MODE_RAW,  PROJ, MM);
    sgemm_ep<<<gg, bb>>>(value, Wg, vg, bg,      MODE_GATE, PROJ, MM);

    // Attention + att_map
    attn_kernel<<<dim3(TT / 64, HH, BB), 256, ATTN_SMEM>>>(qf, kf, vg, ov, att);

    // Output projection
    dim3 go(MM / 128, NTOK / 128);     // (4, 32)
    sgemm_ep<<<go, bb>>>(ov, Wo, out, nullptr, MODE_RAW, MM, PROJ);
}

// round 2
// speedup vs baseline: 1.9072x; 1.9072x over previous
#include <cuda_runtime.h>
#include <mma.h>
#include <math.h>
using namespace nvcuda;

// Problem constants
#define BB 4
#define TT 1024
#define MM 512
#define HH 8
#define DK 64
#define DV 64
#define NTOK (BB*TT)          // 4096
#define PROJ (HH*DK)          // 512

// Scratch (no cudaMalloc allowed)
__device__ float g_qf[NTOK*PROJ];
__device__ float g_kf[NTOK*PROJ];
__device__ float g_v [NTOK*PROJ];
__device__ float g_o [NTOK*PROJ];

enum { MODE_PHI = 0, MODE_RAW = 1, MODE_GATE = 2 };

// ---------------------------------------------------------------------------
// TF32 tensor-core GEMM: C[Mr,N] = A[Mr,Kd] @ Bw[Kd,N], fused epilogue.
// BM=128, BN=64, BK=32, 256 threads (8 warps), warp tile 32x32 (2x2 wmma).
// ---------------------------------------------------------------------------
#define GBM 128
#define GBN 64
#define GBK 32
#define LDA 40
#define LDB 72
#define LDC 72

__global__ __launch_bounds__(256) void gemm_tc(
    const float* __restrict__ A, const float* __restrict__ Bw,
    float* __restrict__ C, const float* __restrict__ bias,
    int mode, int N, int Kd)
{
    __shared__ __align__(16) char smem_raw[GBM * LDC * 4];   // 36864 B
    float (*As)[LDA] = (float(*)[LDA])smem_raw;              // 128x40 = 20480
    float (*Bs)[LDB] = (float(*)[LDB])(smem_raw + GBM * LDA * 4); // 32x72 = 9216
    float (*Cs)[LDC] = (float(*)[LDC])smem_raw;              // aliases A/B after k-loop

    const int tid = threadIdx.x;
    const int wid = tid >> 5;
    const int wr = wid >> 1;      // 0..3
    const int wc = wid & 1;       // 0..1
    const int row0 = blockIdx.y * GBM;
    const int col0 = blockIdx.x * GBN;

    wmma::fragment<wmma::accumulator, 16, 16, 8, float> acc[2][2];
    #pragma unroll
    for (int i = 0; i < 2; i++)
        #pragma unroll
        for (int j = 0; j < 2; j++) wmma::fill_fragment(acc[i][j], 0.f);

    for (int k0 = 0; k0 < Kd; k0 += GBK) {
        // Load A tile 128x32 (4 passes of 32 rows)
        #pragma unroll
        for (int p = 0; p < 4; p++) {
            int r = (tid >> 3) + p * 32;
            int c = (tid & 7) * 4;
            float4 v = *(const float4*)(A + (size_t)(row0 + r) * Kd + k0 + c);
            As[r][c + 0] = wmma::__float_to_tf32(v.x);
            As[r][c + 1] = wmma::__float_to_tf32(v.y);
            As[r][c + 2] = wmma::__float_to_tf32(v.z);
            As[r][c + 3] = wmma::__float_to_tf32(v.w);
        }
        // Load B tile 32x64 (2 passes of 16 rows)
        #pragma unroll
        for (int p = 0; p < 2; p++) {
            int r = (tid >> 4) + p * 16;
            int c = (tid & 15) * 4;
            float4 v = *(const float4*)(Bw + (size_t)(k0 + r) * N + col0 + c);
            Bs[r][c + 0] = wmma::__float_to_tf32(v.x);
            Bs[r][c + 1] = wmma::__float_to_tf32(v.y);
            Bs[r][c + 2] = wmma::__float_to_tf32(v.z);
            Bs[r][c + 3] = wmma::__float_to_tf32(v.w);
        }
        __syncthreads();

        #pragma unroll
        for (int kk = 0; kk < GBK; kk += 8) {
            wmma::fragment<wmma::matrix_a, 16, 16, 8, wmma::precision::tf32, wmma::row_major> af[2];
            wmma::fragment<wmma::matrix_b, 16, 16, 8, wmma::precision::tf32, wmma::row_major> bf[2];
            #pragma unroll
            for (int i = 0; i < 2; i++)
                wmma::load_matrix_sync(af[i], &As[wr * 32 + i * 16][kk], LDA);
            #pragma unroll
            for (int j = 0; j < 2; j++)
                wmma::load_matrix_sync(bf[j], &Bs[kk][wc * 32 + j * 16], LDB);
            #pragma unroll
            for (int i = 0; i < 2; i++)
                #pragma unroll
                for (int j = 0; j < 2; j++)
                    wmma::mma_sync(acc[i][j], af[i], bf[j], acc[i][j]);
        }
        __syncthreads();
    }

    // Stage accumulators to smem, then fused epilogue with coalesced writes
    #pragma unroll
    for (int i = 0; i < 2; i++)
        #pragma unroll
        for (int j = 0; j < 2; j++)
            wmma::store_matrix_sync(&Cs[wr * 32 + i * 16][wc * 32 + j * 16],
                                    acc[i][j], LDC, wmma::mem_row_major);
    __syncthreads();

    for (int e = tid; e < GBM * GBN; e += 256) {
        int r = e >> 6, c = e & 63;
        size_t idx = (size_t)(row0 + r) * N + col0 + c;
        float v = Cs[r][c];
        if (mode == MODE_PHI) {
            C[idx] = (v > 0.f) ? (v + 1.f) : expf(v);   // phi = elu+1
        } else if (mode == MODE_RAW) {
            C[idx] = v;
        } else {  // MODE_GATE
            float g = v + bias[col0 + c];
            C[idx] = C[idx] * (2.f / (1.f + expf(-g)));
        }
    }
}

// ---------------------------------------------------------------------------
// TF32 tensor-core causal attention per (b, h, 64-row tile).
// Phase 1: S = QK^T (masked) -> rowsum, O += S @ V.
// Phase 2: recompute S, write att_map = S * inv_denom (upper tri zeroed).
// ---------------------------------------------------------------------------
#define ALD 72

__global__ __launch_bounds__(256) void attn_tc(
    const float* __restrict__ qf, const float* __restrict__ kf,
    const float* __restrict__ vg, float* __restrict__ o,
    float* __restrict__ att)
{
    extern __shared__ float sm[];
    float (*Qs)[ALD] = (float(*)[ALD])(sm);
    float (*Ks)[ALD] = (float(*)[ALD])(sm + 64 * ALD);
    float (*Vs)[ALD] = (float(*)[ALD])(sm + 2 * 64 * ALD);
    float (*Ss)[ALD] = (float(*)[ALD])(sm + 3 * 64 * ALD);
    float* rowsum    = sm + 4 * 64 * ALD;
    float* inv       = rowsum + 64;

    const int tid = threadIdx.x;
    const int wid = tid >> 5;
    const int wr = wid >> 1;      // 0..3 (16-row strips)
    const int wc = wid & 1;       // 0..1 (32-col strips)
    const int rt = blockIdx.x;    // 0..15
    const int h  = blockIdx.y;
    const int b  = blockIdx.z;
    const int t0 = rt * 64;

    // Load Q tile (convert to tf32)
    for (int e = tid; e < 64 * 64; e += 256) {
        int r = e >> 6, c = e & 63;
        Qs[r][c] = wmma::__float_to_tf32(
            qf[((size_t)(b * TT + t0 + r)) * PROJ + h * DK + c]);
    }
    if (tid < 64) rowsum[tid] = 0.f;

    wmma::fragment<wmma::accumulator, 16, 16, 8, float> acc_o[2];
    wmma::fill_fragment(acc_o[0], 0.f);
    wmma::fill_fragment(acc_o[1], 0.f);

    // ---- Phase 1 ----
    for (int jt = 0; jt <= rt; jt++) {
        __syncthreads();
        const int s0 = jt * 64;
        for (int e = tid; e < 64 * 64; e += 256) {
            int r = e >> 6, c = e & 63;
            size_t gi = ((size_t)(b * TT + s0 + r)) * PROJ + h * DK + c;
            Ks[r][c] = wmma::__float_to_tf32(kf[gi]);
            Vs[r][c] = wmma::__float_to_tf32(vg[gi]);
        }
        __syncthreads();

        // S = Q @ K^T
        wmma::fragment<wmma::accumulator, 16, 16, 8, float> acc_s[2];
        wmma::fill_fragment(acc_s[0], 0.f);
        wmma::fill_fragment(acc_s[1], 0.f);
        #pragma unroll
        for (int kk = 0; kk < 64; kk += 8) {
            wmma::fragment<wmma::matrix_a, 16, 16, 8, wmma::precision::tf32, wmma::row_major> af;
            wmma::fragment<wmma::matrix_b, 16, 16, 8, wmma::precision::tf32, wmma::col_major> bf[2];
            wmma::load_matrix_sync(af, &Qs[wr * 16][kk], ALD);
            wmma::load_matrix_sync(bf[0], &Ks[wc * 32][kk], ALD);
            wmma::load_matrix_sync(bf[1], &Ks[wc * 32 + 16][kk], ALD);
            wmma::mma_sync(acc_s[0], af, bf[0], acc_s[0]);
            wmma::mma_sync(acc_s[1], af, bf[1], acc_s[1]);
        }
        wmma::store_matrix_sync(&Ss[wr * 16][wc * 32], acc_s[0], ALD, wmma::mem_row_major);
        wmma::store_matrix_sync(&Ss[wr * 16][wc * 32 + 16], acc_s[1], ALD, wmma::mem_row_major);
        __syncthreads();

        // Mask (diagonal tile) + convert to tf32 for the S@V mma
        if (jt == rt) {
            for (int e = tid; e < 64 * 64; e += 256) {
                int r = e >> 6, c = e & 63;
                float v = (c > r) ? 0.f : Ss[r][c];
                Ss[r][c] = wmma::__float_to_tf32(v);
            }
        } else {
            for (int e = tid; e < 64 * 64; e += 256) {
                int r = e >> 6, c = e & 63;
                Ss[r][c] = wmma::__float_to_tf32(Ss[r][c]);
            }
        }
        __syncthreads();

        if (tid < 64) {
            float rs = 0.f;
            #pragma unroll 8
            for (int c = 0; c < 64; c++) rs += Ss[tid][c];
            rowsum[tid] += rs;
        }

        // O += S @ V
        #pragma unroll
        for (int kk = 0; kk < 64; kk += 8) {
            wmma::fragment<wmma::matrix_a, 16, 16, 8, wmma::precision::tf32, wmma::row_major> af;
            wmma::fragment<wmma::matrix_b, 16, 16, 8, wmma::precision::tf32, wmma::row_major> bf[2];
            wmma::load_matrix_sync(af, &Ss[wr * 16][kk], ALD);
            wmma::load_matrix_sync(bf[0], &Vs[kk][wc * 32], ALD);
            wmma::load_matrix_sync(bf[1], &Vs[kk][wc * 32 + 16], ALD);
            wmma::mma_sync(acc_o[0], af, bf[0], acc_o[0]);
            wmma::mma_sync(acc_o[1], af, bf[1], acc_o[1]);
        }
    }
    __syncthreads();

    if (tid < 64) inv[tid] = 1.f / (rowsum[tid] + 1e-6f);
    __syncthreads();

    // Write O = numer * inv_denom
    wmma::store_matrix_sync(&Ss[wr * 16][wc * 32], acc_o[0], ALD, wmma::mem_row_major);
    wmma::store_matrix_sync(&Ss[wr * 16][wc * 32 + 16], acc_o[1], ALD, wmma::mem_row_major);
    __syncthreads();
    for (int e = tid; e < 64 * 64; e += 256) {
        int r = e >> 6, c = e & 63;
        o[((size_t)(b * TT + t0 + r)) * PROJ + h * DV + c] = Ss[r][c] * inv[r];
    }

    // ---- Phase 2: att_map ----
    const size_t attBase = ((size_t)(b * HH + h)) * TT * TT;
    for (int jt = 0; jt < TT / 64; jt++) {
        const int s0 = jt * 64;
        if (jt <= rt) {
            __syncthreads();
            for (int e = tid; e < 64 * 64; e += 256) {
                int r = e >> 6, c = e & 63;
                Ks[r][c] = wmma::__float_to_tf32(
                    kf[((size_t)(b * TT + s0 + r)) * PROJ + h * DK + c]);
            }
            __syncthreads();
            wmma::fragment<wmma::accumulator, 16, 16, 8, float> acc_s[2];
            wmma::fill_fragment(acc_s[0], 0.f);
            wmma::fill_fragment(acc_s[1], 0.f);
            #pragma unroll
            for (int kk = 0; kk < 64; kk += 8) {
                wmma::fragment<wmma::matrix_a, 16, 16, 8, wmma::precision::tf32, wmma::row_major> af;
                wmma::fragment<wmma::matrix_b, 16, 16, 8, wmma::precision::tf32, wmma::col_major> bf[2];
                wmma::load_matrix_sync(af, &Qs[wr * 16][kk], ALD);
                wmma::load_matrix_sync(bf[0], &Ks[wc * 32][kk], ALD);
                wmma::load_matrix_sync(bf[1], &Ks[wc * 32 + 16][kk], ALD);
                wmma::mma_sync(acc_s[0], af, bf[0], acc_s[0]);
                wmma::mma_sync(acc_s[1], af, bf[1], acc_s[1]);
            }
            wmma::store_matrix_sync(&Ss[wr * 16][wc * 32], acc_s[0], ALD, wmma::mem_row_major);
            wmma::store_matrix_sync(&Ss[wr * 16][wc * 32 + 16], acc_s[1], ALD, wmma::mem_row_major);
            __syncthreads();
            for (int e = tid; e < 64 * 64; e += 256) {
                int r = e >> 6, c = e & 63;
                float v = Ss[r][c] * inv[r];
                if (jt == rt && c > r) v = 0.f;
                att[attBase + (size_t)(t0 + r) * TT + s0 + c] = v;
            }
        } else {
            for (int e = tid; e < 64 * 64; e += 256) {
                int r = e >> 6, c = e & 63;
                att[attBase + (size_t)(t0 + r) * TT + s0 + c] = 0.f;
            }
        }
    }
}

// ---------------------------------------------------------------------------
extern "C" void kernel_launch(void* const* d_in, const int* in_sizes, int n_in,
                              void* d_out, int out_size)
{
    const float* query = (const float*)d_in[0];
    const float* key   = (const float*)d_in[1];
    const float* value = (const float*)d_in[2];
    const float* Wq    = (const float*)d_in[3];
    const float* Wk    = (const float*)d_in[4];
    const float* Wv    = (const float*)d_in[5];
    const float* Wg    = (const float*)d_in[6];
    const float* bg    = (const float*)d_in[7];
    const float* Wo    = (const float*)d_in[8];

    float* out = (float*)d_out;                       // [B,T,M]
    float* att = out + (size_t)NTOK * MM;             // [B,H,T,T]

    float *qf, *kf, *vg, *ov;
    cudaGetSymbolAddress((void**)&qf, g_qf);
    cudaGetSymbolAddress((void**)&kf, g_kf);
    cudaGetSymbolAddress((void**)&vg, g_v);
    cudaGetSymbolAddress((void**)&ov, g_o);

    const int ATTN_SMEM = (4 * 64 * ALD + 128) * (int)sizeof(float); // ~74 KB
    cudaFuncSetAttribute(attn_tc,
                         cudaFuncAttributeMaxDynamicSharedMemorySize, ATTN_SMEM);

    dim3 bb(256);
    dim3 gg(PROJ / GBN, NTOK / GBM);   // (8, 32) = 256 blocks

    // Projections (tensor core)
    gemm_tc<<<gg, bb>>>(query, Wq, qf, nullptr, MODE_PHI,  PROJ, MM);
    gemm_tc<<<gg, bb>>>(key,   Wk, kf, nullptr, MODE_PHI,  PROJ, MM);
    gemm_tc<<<gg, bb>>>(value, Wv, vg, nullptr, MODE_RAW,  PROJ, MM);
    gemm_tc<<<gg, bb>>>(value, Wg, vg, bg,      MODE_GATE, PROJ, MM);

    // Attention + att_map
    attn_tc<<<dim3(TT / 64, HH, BB), 256, ATTN_SMEM>>>(qf, kf, vg, ov, att);

    // Output projection
    dim3 go(MM / GBN, NTOK / GBM);     // (8, 32)
    gemm_tc<<<go, bb>>>(ov, Wo, out, nullptr, MODE_RAW, MM, PROJ);
}